// round 6
// baseline (speedup 1.0000x reference)
#include <cuda_runtime.h>

#define NFEAT 8192
#define PDIM 256
#define RDIM 512
#define MROWS 32
#define NROWS 2048   // M*A
#define NSTACKS 32
#define NS 4
#define KSPLIT 4
#define KCHUNK (RDIM / KSPLIT)   // 128

#define BM 64
#define BN 64
#define BK 32

typedef unsigned long long ull;
typedef unsigned int uint;

// scratch (static device globals; no allocation in kernel_launch)
__device__ float g_proj4[KSPLIT * NROWS * PDIM];   // split-K partial projections
__device__ int   g_cnt[NS];
__device__ int   g_off[NS];
__device__ int   g_flat[NROWS];                    // rows sorted by charge
__device__ unsigned char g_dsign[NS * NSTACKS * 32]; // packed D sign bits per lane
__device__ float g_partial[NROWS * 4];             // 4 stack-groups per (m,a)
__device__ int   g_done;

__device__ __forceinline__ ull pack2(float lo, float hi) {
    ull d;
    asm("mov.b64 %0, {%1, %2};" : "=l"(d) : "r"(__float_as_uint(lo)), "r"(__float_as_uint(hi)));
    return d;
}
__device__ __forceinline__ ull fma2(ull a, ull b, ull c) {
    ull d;
    asm("fma.rn.f32x2 %0, %1, %2, %3;" : "=l"(d) : "l"(a), "l"(b), "l"(c));
    return d;
}
__device__ __forceinline__ void unpack2(ull v, float& lo, float& hi) {
    unsigned int l, h;
    asm("mov.b64 {%0, %1}, %2;" : "=r"(l), "=r"(h) : "l"(v));
    lo = __uint_as_float(l); hi = __uint_as_float(h);
}

// classify rows by charge into a flat sorted list, pack D signs, reset done flag.
// List order within a charge is atomic-order dependent, but it only selects which
// warp processes which row; every row's arithmetic and output slot are fixed, so
// final output bits are deterministic.
__global__ void k_classify(const int* __restrict__ charges,
                           const float* __restrict__ Dmat) {
    __shared__ int scnt[NS];
    __shared__ int scur[NS];
    int t = threadIdx.x;
    if (t < NS) scnt[t] = 0;
    if (t == 0) g_done = 0;
    __syncthreads();
    #pragma unroll
    for (int row = t; row < NROWS; row += 1024)
        atomicAdd(&scnt[charges[row]], 1);
    __syncthreads();
    if (t == 0) {
        int o = 0;
        for (int s = 0; s < NS; s++) {
            g_cnt[s] = scnt[s];
            g_off[s] = o;
            scur[s] = o;
            o += scnt[s];
        }
    }
    __syncthreads();
    #pragma unroll
    for (int row = t; row < NROWS; row += 1024) {
        int s = charges[row];
        int pos = atomicAdd(&scur[s], 1);
        g_flat[pos] = row;
    }
    // pack D sign bits: bit j of byte (s,st,lane) = (D[s,st,lane*8+j] < 0)
    for (int i = t; i < NS * NSTACKS * 32; i += 1024) {
        int lane = i & 31;
        const float* dp = Dmat + (i >> 5) * PDIM + lane * 8;
        uint b = 0;
        #pragma unroll
        for (int j = 0; j < 8; j++)
            b |= (__float_as_uint(dp[j]) >> 31) << j;
        g_dsign[i] = (unsigned char)b;
    }
}

// Charge-grouped split-K GEMM (rows gathered via g_flat/g_off)
__global__ void k_gemm(const float* __restrict__ rep,
                       const float* __restrict__ reductors) {
    int s = blockIdx.z;
    int cnt = g_cnt[s];
    int row0 = blockIdx.y * BM;
    if (row0 >= cnt) return;
    int base = g_off[s];

    int ntile  = blockIdx.x & 3;
    int kslice = blockIdx.x >> 2;
    int k0 = kslice * KCHUNK;

    __shared__ int   rowIdx[BM];
    __shared__ float As[BK][BM];
    __shared__ float Bs[BK][BN];

    int t  = threadIdx.x;
    int tx = t & 15;
    int ty = t >> 4;

    if (t < BM) {
        int gi = row0 + t;
        rowIdx[t] = (gi < cnt) ? g_flat[base + gi] : -1;
    }
    __syncthreads();

    ull acc2[4][2] = {};
    const float* redS = reductors + s * RDIM * PDIM + ntile * BN;

    for (int kb = k0; kb < k0 + KCHUNK; kb += BK) {
        #pragma unroll
        for (int i = 0; i < 2; i++) {
            int slot = t * 2 + i;
            int r  = slot >> 3;
            int kq = slot & 7;
            int grow = rowIdx[r];
            float4 v = make_float4(0.f, 0.f, 0.f, 0.f);
            if (grow >= 0)
                v = *(const float4*)(rep + grow * RDIM + kb + kq * 4);
            As[kq * 4 + 0][r] = v.x;
            As[kq * 4 + 1][r] = v.y;
            As[kq * 4 + 2][r] = v.z;
            As[kq * 4 + 3][r] = v.w;
        }
        #pragma unroll
        for (int i = 0; i < 2; i++) {
            int slot = t * 2 + i;
            int k  = slot >> 4;
            int cq = slot & 15;
            float4 v = *(const float4*)(redS + (kb + k) * PDIM + cq * 4);
            *(float4*)&Bs[k][cq * 4] = v;
        }
        __syncthreads();

        #pragma unroll
        for (int k = 0; k < BK; k++) {
            float4 a4 = *(const float4*)&As[k][ty * 4];
            float4 b4 = *(const float4*)&Bs[k][tx * 4];
            ull a01 = pack2(a4.x, a4.y);
            ull a23 = pack2(a4.z, a4.w);
            float bv[4] = {b4.x, b4.y, b4.z, b4.w};
            #pragma unroll
            for (int jj = 0; jj < 4; jj++) {
                ull bd = pack2(bv[jj], bv[jj]);
                acc2[jj][0] = fma2(a01, bd, acc2[jj][0]);
                acc2[jj][1] = fma2(a23, bd, acc2[jj][1]);
            }
        }
        __syncthreads();
    }

    float acc[4][4];
    #pragma unroll
    for (int jj = 0; jj < 4; jj++) {
        unpack2(acc2[jj][0], acc[0][jj], acc[1][jj]);
        unpack2(acc2[jj][1], acc[2][jj], acc[3][jj]);
    }

    float* outSlice = g_proj4 + kslice * (NROWS * PDIM);
    #pragma unroll
    for (int ii = 0; ii < 4; ii++) {
        int r = rowIdx[ty * 4 + ii];
        if (r >= 0) {
            float4 v = make_float4(acc[ii][0], acc[ii][1], acc[ii][2], acc[ii][3]);
            *(float4*)(outSlice + r * PDIM + ntile * BN + tx * 4) = v;
        }
    }
}

// FWHT-256 + cos-dot for one stack, given packed proj bits, D sign byte, and
// permuted bias/alpha. Half-exchange lane stages: element (lane q, reg r) ends
// at logical index 128*(r>>2) + (q>>1)*8 + (q&1)*4 + (r&3); bias/alpha are
// loaded at the matching permuted bases (two contiguous float4 runs).
__device__ __forceinline__ float stackwork(const uint* __restrict__ projb,
                                           uint dbyte, int lane,
                                           const float* __restrict__ bb,
                                           const float* __restrict__ aa) {
    float v[8];
    #pragma unroll
    for (int j = 0; j < 8; j++)
        v[j] = __uint_as_float(projb[j] ^ ((dbyte << (31 - j)) & 0x80000000u));

    float tv;
    tv = v[0]; v[0] = tv + v[1]; v[1] = tv - v[1];
    tv = v[2]; v[2] = tv + v[3]; v[3] = tv - v[3];
    tv = v[4]; v[4] = tv + v[5]; v[5] = tv - v[5];
    tv = v[6]; v[6] = tv + v[7]; v[7] = tv - v[7];

    tv = v[0]; v[0] = tv + v[2]; v[2] = tv - v[2];
    tv = v[1]; v[1] = tv + v[3]; v[3] = tv - v[3];
    tv = v[4]; v[4] = tv + v[6]; v[6] = tv - v[6];
    tv = v[5]; v[5] = tv + v[7]; v[7] = tv - v[7];

    tv = v[0]; v[0] = tv + v[4]; v[4] = tv - v[4];
    tv = v[1]; v[1] = tv + v[5]; v[5] = tv - v[5];
    tv = v[2]; v[2] = tv + v[6]; v[6] = tv - v[6];
    tv = v[3]; v[3] = tv + v[7]; v[7] = tv - v[7];

    #pragma unroll
    for (int msk = 1; msk <= 16; msk <<= 1) {
        bool hi = (lane & msk) != 0;
        float sgn = hi ? -1.f : 1.f;
        float nv[8];
        #pragma unroll
        for (int r = 0; r < 4; r++) {
            float send = hi ? v[r]     : v[r + 4];
            float keep = hi ? v[r + 4] : v[r];
            float recv = __shfl_xor_sync(0xffffffffu, send, msk);
            nv[r]     = keep + recv;
            nv[r + 4] = (keep - recv) * sgn;
        }
        #pragma unroll
        for (int r = 0; r < 8; r++) v[r] = nv[r];
    }

    float acc = 0.f;
    #pragma unroll
    for (int j = 0; j < 8; j++)
        acc += __cosf(v[j] + bb[j]) * aa[j];
    return acc;
}

// One warp per (row-pair, stack-group): 4096 warps. The two rows come from
// adjacent slots of the charge-sorted list so they (almost always) share s and
// hence D/bias/alpha operands -> load once, use twice. The final reduction is
// fused via last-block-done (fixed-order, deterministic).
__global__ void __launch_bounds__(256)
k_feat(const int* __restrict__ charges,
       const float* __restrict__ bias,
       const float* __restrict__ alpha,
       float* __restrict__ out) {
    int warpId = threadIdx.x >> 5;
    int lane   = threadIdx.x & 31;
    int task   = blockIdx.x * 8 + warpId;   // 0..4095
    int pp     = task >> 2;
    int grp    = task & 3;
    int st0    = grp * 8;

    int row0 = g_flat[2 * pp];
    int row1 = g_flat[2 * pp + 1];
    int s0 = charges[row0];
    int s1 = charges[row1];

    uint projb0[8], projb1[8];
    {
        float acc0[8], acc1[8];
        #pragma unroll
        for (int c = 0; c < KSPLIT; c++) {
            const float* p0 = g_proj4 + c * (NROWS * PDIM) + row0 * PDIM + lane * 8;
            const float* p1 = g_proj4 + c * (NROWS * PDIM) + row1 * PDIM + lane * 8;
            float4 x0 = *(const float4*)p0;
            float4 x1 = *(const float4*)(p0 + 4);
            float4 y0 = *(const float4*)p1;
            float4 y1 = *(const float4*)(p1 + 4);
            if (c == 0) {
                acc0[0]=x0.x; acc0[1]=x0.y; acc0[2]=x0.z; acc0[3]=x0.w;
                acc0[4]=x1.x; acc0[5]=x1.y; acc0[6]=x1.z; acc0[7]=x1.w;
                acc1[0]=y0.x; acc1[1]=y0.y; acc1[2]=y0.z; acc1[3]=y0.w;
                acc1[4]=y1.x; acc1[5]=y1.y; acc1[6]=y1.z; acc1[7]=y1.w;
            } else {
                acc0[0]+=x0.x; acc0[1]+=x0.y; acc0[2]+=x0.z; acc0[3]+=x0.w;
                acc0[4]+=x1.x; acc0[5]+=x1.y; acc0[6]+=x1.z; acc0[7]+=x1.w;
                acc1[0]+=y0.x; acc1[1]+=y0.y; acc1[2]+=y0.z; acc1[3]+=y0.w;
                acc1[4]+=y1.x; acc1[5]+=y1.y; acc1[6]+=y1.z; acc1[7]+=y1.w;
            }
        }
        // fold FWHT normalization 1/16 (COEFF_NORM == 1 exactly)
        #pragma unroll
        for (int j = 0; j < 8; j++) {
            projb0[j] = __float_as_uint(acc0[j] * 0.0625f);
            projb1[j] = __float_as_uint(acc1[j] * 0.0625f);
        }
    }

    int pbase = ((lane >> 1) << 3) + ((lane & 1) << 2);
    bool sameS = (s0 == s1);

    float sum0 = 0.f, sum1 = 0.f;
    for (int st = st0; st < st0 + 8; st++) {
        uint d0 = g_dsign[(s0 * NSTACKS + st) * 32 + lane];
        const float* bp = bias + s0 * NFEAT + st * PDIM + pbase;
        const float* ap = alpha + st * PDIM + pbase;
        float4 bx = *(const float4*)bp;
        float4 by = *(const float4*)(bp + 128);
        float4 ax = *(const float4*)ap;
        float4 ay = *(const float4*)(ap + 128);
        float bb[8] = {bx.x, bx.y, bx.z, bx.w, by.x, by.y, by.z, by.w};
        float aa[8] = {ax.x, ax.y, ax.z, ax.w, ay.x, ay.y, ay.z, ay.w};

        sum0 += stackwork(projb0, d0, lane, bb, aa);

        if (sameS) {
            sum1 += stackwork(projb1, d0, lane, bb, aa);
        } else {
            uint d1 = g_dsign[(s1 * NSTACKS + st) * 32 + lane];
            const float* bq = bias + s1 * NFEAT + st * PDIM + pbase;
            float4 cx = *(const float4*)bq;
            float4 cy = *(const float4*)(bq + 128);
            float b2[8] = {cx.x, cx.y, cx.z, cx.w, cy.x, cy.y, cy.z, cy.w};
            sum1 += stackwork(projb1, d1, lane, b2, aa);
        }
    }

    #pragma unroll
    for (int off = 16; off; off >>= 1) {
        sum0 += __shfl_down_sync(0xffffffffu, sum0, off);
        sum1 += __shfl_down_sync(0xffffffffu, sum1, off);
    }
    if (lane == 0) {
        g_partial[row0 * 4 + grp] = sum0;   // index = m*256 + a*4 + grp
        g_partial[row1 * 4 + grp] = sum1;
    }

    // fused final reduction: last block to finish sums in fixed order
    __shared__ int isLast;
    __threadfence();
    __syncthreads();
    if (threadIdx.x == 0)
        isLast = (atomicAdd(&g_done, 1) == (int)gridDim.x - 1);
    __syncthreads();
    if (isLast) {
        __threadfence();
        int t = threadIdx.x;            // 256 threads
        int m = t >> 3;
        int chunk = t & 7;
        const float* p = g_partial + m * 256 + chunk * 32;
        float v = 0.f;
        #pragma unroll
        for (int i = 0; i < 32; i++) v += p[i];
        #pragma unroll
        for (int off = 4; off; off >>= 1)
            v += __shfl_down_sync(0xffffffffu, v, off, 8);
        if (chunk == 0) out[m] = v * 0.015625f;   // FEAT_NORM = 1/64
    }
}

extern "C" void kernel_launch(void* const* d_in, const int* in_sizes, int n_in,
                              void* d_out, int out_size) {
    const float* rep       = (const float*)d_in[0];
    const int*   charges   = (const int*)d_in[1];
    const float* reductors = (const float*)d_in[2];
    const float* Dmat      = (const float*)d_in[3];
    const float* bias      = (const float*)d_in[4];
    const float* alpha     = (const float*)d_in[5];
    float* out = (float*)d_out;

    k_classify<<<1, 1024>>>(charges, Dmat);
    dim3 gg(4 * KSPLIT, NROWS / BM, NS);   // (16, 32, 4); empty row-blocks exit early
    k_gemm<<<gg, 256>>>(rep, reductors);
    k_feat<<<512, 256>>>(charges, bias, alpha, out);   // 4096 warps, fused reduce
}

// round 7
// speedup vs baseline: 1.0174x; 1.0174x over previous
#include <cuda_runtime.h>

#define NFEAT 8192
#define PDIM 256
#define RDIM 512
#define MROWS 32
#define NROWS 2048   // M*A
#define NSTACKS 32
#define NS 4
#define KSPLIT 4
#define KCHUNK (RDIM / KSPLIT)   // 128

#define BM 64
#define BN 64
#define BK 32

typedef unsigned long long ull;
typedef unsigned int uint;

// scratch (static device globals; no allocation in kernel_launch)
__device__ float g_proj4[KSPLIT * NROWS * PDIM];   // split-K partial projections
__device__ int   g_cnt[NS];
__device__ int   g_list[NS * NROWS];               // per-charge row segments
__device__ unsigned char g_dsign[NS * NSTACKS * 32]; // packed D sign bits per lane
__device__ float g_partial[NROWS * 4];             // 4 stack-groups per (m,a)
__device__ int   g_done;

__device__ __forceinline__ ull pack2(float lo, float hi) {
    ull d;
    asm("mov.b64 %0, {%1, %2};" : "=l"(d) : "r"(__float_as_uint(lo)), "r"(__float_as_uint(hi)));
    return d;
}
__device__ __forceinline__ ull fma2(ull a, ull b, ull c) {
    ull d;
    asm("fma.rn.f32x2 %0, %1, %2, %3;" : "=l"(d) : "l"(a), "l"(b), "l"(c));
    return d;
}
__device__ __forceinline__ void unpack2(ull v, float& lo, float& hi) {
    unsigned int l, h;
    asm("mov.b64 {%0, %1}, %2;" : "=r"(l), "=r"(h) : "l"(v));
    lo = __uint_as_float(l); hi = __uint_as_float(h);
}

// Two concurrent blocks: block 0 = single-pass classify into per-charge
// segments; block 1 = pack D sign bits. List order within a charge is
// atomic-order dependent but only selects which GEMM tile handles which row;
// each row's arithmetic and output slot are fixed -> deterministic output.
__global__ void k_prep(const int* __restrict__ charges,
                       const float* __restrict__ Dmat) {
    int t = threadIdx.x;
    if (blockIdx.x == 0) {
        __shared__ int scnt[NS];
        if (t < NS) scnt[t] = 0;
        if (t == 0) g_done = 0;
        __syncthreads();
        for (int row = t; row < NROWS; row += 1024) {
            int s = charges[row];
            int pos = atomicAdd(&scnt[s], 1);
            g_list[s * NROWS + pos] = row;
        }
        __syncthreads();
        if (t < NS) g_cnt[t] = scnt[t];
    } else {
        // pack D sign bits: bit j of byte (s,st,lane) = signbit(D[s,st,lane*8+j])
        for (int i = t; i < NS * NSTACKS * 32; i += 1024) {
            int lane = i & 31;
            const float* dp = Dmat + (i >> 5) * PDIM + lane * 8;
            uint b = 0;
            #pragma unroll
            for (int j = 0; j < 8; j++)
                b |= (__float_as_uint(dp[j]) >> 31) << j;
            g_dsign[i] = (unsigned char)b;
        }
    }
}

// Charge-grouped split-K GEMM:
// g_proj4[kslice][row, :] = rep[row, k0:k0+128] @ reductors[charge(row)][k0:k0+128, :]
__global__ void k_gemm(const float* __restrict__ rep,
                       const float* __restrict__ reductors) {
    int s = blockIdx.z;
    int cnt = g_cnt[s];
    int row0 = blockIdx.y * BM;
    if (row0 >= cnt) return;

    int ntile  = blockIdx.x & 3;
    int kslice = blockIdx.x >> 2;
    int k0 = kslice * KCHUNK;

    __shared__ int   rowIdx[BM];
    __shared__ float As[BK][BM];
    __shared__ float Bs[BK][BN];

    int t  = threadIdx.x;
    int tx = t & 15;
    int ty = t >> 4;

    if (t < BM) {
        int gi = row0 + t;
        rowIdx[t] = (gi < cnt) ? g_list[s * NROWS + gi] : -1;
    }
    __syncthreads();

    ull acc2[4][2] = {};
    const float* redS = reductors + s * RDIM * PDIM + ntile * BN;

    for (int kb = k0; kb < k0 + KCHUNK; kb += BK) {
        #pragma unroll
        for (int i = 0; i < 2; i++) {
            int slot = t * 2 + i;
            int r  = slot >> 3;
            int kq = slot & 7;
            int grow = rowIdx[r];
            float4 v = make_float4(0.f, 0.f, 0.f, 0.f);
            if (grow >= 0)
                v = *(const float4*)(rep + grow * RDIM + kb + kq * 4);
            As[kq * 4 + 0][r] = v.x;
            As[kq * 4 + 1][r] = v.y;
            As[kq * 4 + 2][r] = v.z;
            As[kq * 4 + 3][r] = v.w;
        }
        #pragma unroll
        for (int i = 0; i < 2; i++) {
            int slot = t * 2 + i;
            int k  = slot >> 4;
            int cq = slot & 15;
            float4 v = *(const float4*)(redS + (kb + k) * PDIM + cq * 4);
            *(float4*)&Bs[k][cq * 4] = v;
        }
        __syncthreads();

        #pragma unroll
        for (int k = 0; k < BK; k++) {
            float4 a4 = *(const float4*)&As[k][ty * 4];
            float4 b4 = *(const float4*)&Bs[k][tx * 4];
            ull a01 = pack2(a4.x, a4.y);
            ull a23 = pack2(a4.z, a4.w);
            float bv[4] = {b4.x, b4.y, b4.z, b4.w};
            #pragma unroll
            for (int jj = 0; jj < 4; jj++) {
                ull bd = pack2(bv[jj], bv[jj]);
                acc2[jj][0] = fma2(a01, bd, acc2[jj][0]);
                acc2[jj][1] = fma2(a23, bd, acc2[jj][1]);
            }
        }
        __syncthreads();
    }

    float acc[4][4];
    #pragma unroll
    for (int jj = 0; jj < 4; jj++) {
        unpack2(acc2[jj][0], acc[0][jj], acc[1][jj]);
        unpack2(acc2[jj][1], acc[2][jj], acc[3][jj]);
    }

    float* outSlice = g_proj4 + kslice * (NROWS * PDIM);
    #pragma unroll
    for (int ii = 0; ii < 4; ii++) {
        int r = rowIdx[ty * 4 + ii];
        if (r >= 0) {
            float4 v = make_float4(acc[ii][0], acc[ii][1], acc[ii][2], acc[ii][3]);
            *(float4*)(outSlice + r * PDIM + ntile * BN + tx * 4) = v;
        }
    }
}

// One warp per (pair, stack-group): 8192 tasks (R5 shape, register-lean).
// FWHT-256 with half-exchange lane stages; element (lane q, reg r) ends at
// logical index 128*(r>>2) + (q>>1)*8 + (q&1)*4 + (r&3); bias/alpha load at
// the matching permuted bases (two contiguous float4 runs). D signs come from
// the packed byte table. Final reduction fused via last-block-done.
__global__ void __launch_bounds__(256)
k_feat(const int* __restrict__ charges,
       const float* __restrict__ bias,
       const float* __restrict__ alpha,
       float* __restrict__ out) {
    int warpId = threadIdx.x >> 5;
    int lane   = threadIdx.x & 31;
    int task   = blockIdx.x * 8 + warpId;   // 0..8191
    int pair   = task >> 2;
    int grp    = task & 3;
    int st0    = grp * 8;

    int s = charges[pair];

    uint projb[8];
    {
        const float* pp = g_proj4 + pair * PDIM + lane * 8;
        float4 p0 = *(const float4*)pp;
        float4 p1 = *(const float4*)(pp + 4);
        float acc[8] = {p0.x, p0.y, p0.z, p0.w, p1.x, p1.y, p1.z, p1.w};
        #pragma unroll
        for (int c = 1; c < KSPLIT; c++) {
            const float* pc = g_proj4 + c * (NROWS * PDIM) + pair * PDIM + lane * 8;
            float4 q0 = *(const float4*)pc;
            float4 q1 = *(const float4*)(pc + 4);
            acc[0] += q0.x; acc[1] += q0.y; acc[2] += q0.z; acc[3] += q0.w;
            acc[4] += q1.x; acc[5] += q1.y; acc[6] += q1.z; acc[7] += q1.w;
        }
        // fold FWHT normalization 1/16 (COEFF_NORM == 1 exactly)
        #pragma unroll
        for (int j = 0; j < 8; j++) projb[j] = __float_as_uint(acc[j] * 0.0625f);
    }

    const unsigned char* ds = g_dsign + (s * NSTACKS) * 32 + lane;
    const float* bs = bias + s * NFEAT;
    int pbase = ((lane >> 1) << 3) + ((lane & 1) << 2);

    float sum = 0.f;
    for (int st = st0; st < st0 + 8; st++) {
        uint dbyte = ds[st * 32];
        float v[8];
        #pragma unroll
        for (int j = 0; j < 8; j++)
            v[j] = __uint_as_float(projb[j] ^ ((dbyte << (31 - j)) & 0x80000000u));

        float tv;
        tv = v[0]; v[0] = tv + v[1]; v[1] = tv - v[1];
        tv = v[2]; v[2] = tv + v[3]; v[3] = tv - v[3];
        tv = v[4]; v[4] = tv + v[5]; v[5] = tv - v[5];
        tv = v[6]; v[6] = tv + v[7]; v[7] = tv - v[7];

        tv = v[0]; v[0] = tv + v[2]; v[2] = tv - v[2];
        tv = v[1]; v[1] = tv + v[3]; v[3] = tv - v[3];
        tv = v[4]; v[4] = tv + v[6]; v[6] = tv - v[6];
        tv = v[5]; v[5] = tv + v[7]; v[7] = tv - v[7];

        tv = v[0]; v[0] = tv + v[4]; v[4] = tv - v[4];
        tv = v[1]; v[1] = tv + v[5]; v[5] = tv - v[5];
        tv = v[2]; v[2] = tv + v[6]; v[6] = tv - v[6];
        tv = v[3]; v[3] = tv + v[7]; v[7] = tv - v[7];

        #pragma unroll
        for (int msk = 1; msk <= 16; msk <<= 1) {
            bool hi = (lane & msk) != 0;
            float sgn = hi ? -1.f : 1.f;
            float nv[8];
            #pragma unroll
            for (int r = 0; r < 4; r++) {
                float send = hi ? v[r]     : v[r + 4];
                float keep = hi ? v[r + 4] : v[r];
                float recv = __shfl_xor_sync(0xffffffffu, send, msk);
                nv[r]     = keep + recv;
                nv[r + 4] = (keep - recv) * sgn;
            }
            #pragma unroll
            for (int r = 0; r < 8; r++) v[r] = nv[r];
        }

        const float* bp = bs + st * PDIM + pbase;
        const float* ap = alpha + st * PDIM + pbase;
        float4 b0 = *(const float4*)bp;
        float4 b1 = *(const float4*)(bp + 128);
        float4 a0 = *(const float4*)ap;
        float4 a1 = *(const float4*)(ap + 128);
        float bb[8] = {b0.x, b0.y, b0.z, b0.w, b1.x, b1.y, b1.z, b1.w};
        float aa[8] = {a0.x, a0.y, a0.z, a0.w, a1.x, a1.y, a1.z, a1.w};
        #pragma unroll
        for (int j = 0; j < 8; j++)
            sum += __cosf(v[j] + bb[j]) * aa[j];
    }

    #pragma unroll
    for (int off = 16; off; off >>= 1)
        sum += __shfl_down_sync(0xffffffffu, sum, off);
    if (lane == 0) g_partial[task] = sum;   // task = m*256 + a*4 + grp

    // fused final reduction: last block to finish sums in fixed order
    __shared__ int isLast;
    __threadfence();
    __syncthreads();
    if (threadIdx.x == 0)
        isLast = (atomicAdd(&g_done, 1) == (int)gridDim.x - 1);
    __syncthreads();
    if (isLast) {
        __threadfence();
        int t = threadIdx.x;            // 256 threads
        int m = t >> 3;
        int chunk = t & 7;
        const float* p = g_partial + m * 256 + chunk * 32;
        float v = 0.f;
        #pragma unroll
        for (int i = 0; i < 32; i++) v += p[i];
        #pragma unroll
        for (int off = 4; off; off >>= 1)
            v += __shfl_down_sync(0xffffffffu, v, off, 8);
        if (chunk == 0) out[m] = v * 0.015625f;   // FEAT_NORM = 1/64
    }
}

extern "C" void kernel_launch(void* const* d_in, const int* in_sizes, int n_in,
                              void* d_out, int out_size) {
    const float* rep       = (const float*)d_in[0];
    const int*   charges   = (const int*)d_in[1];
    const float* reductors = (const float*)d_in[2];
    const float* Dmat      = (const float*)d_in[3];
    const float* bias      = (const float*)d_in[4];
    const float* alpha     = (const float*)d_in[5];
    float* out = (float*)d_out;

    k_prep<<<2, 1024>>>(charges, Dmat);
    dim3 gg(4 * KSPLIT, NROWS / BM, NS);   // (16, 32, 4); empty row-blocks exit early
    k_gemm<<<gg, 256>>>(rep, reductors);
    k_feat<<<1024, 256>>>(charges, bias, alpha, out);   // 8192 warps, fused reduce
}

// round 9
// speedup vs baseline: 1.1140x; 1.0949x over previous
#include <cuda_runtime.h>

#define NFEAT 8192
#define PDIM 256
#define RDIM 512
#define MROWS 32
#define NROWS 2048   // M*A
#define NSTACKS 32
#define NS 4
#define KSPLIT 4
#define KCHUNK (RDIM / KSPLIT)   // 128

#define BM 64
#define BN 64
#define BK 32

typedef unsigned long long ull;
typedef unsigned int uint;

// scratch (static device globals; no allocation in kernel_launch)
__device__ float g_proj4[KSPLIT * NROWS * PDIM];   // split-K partial projections
__device__ float g_partial[NROWS * 4];             // 4 stack-groups per (m,a)

__device__ __forceinline__ ull pack2(float lo, float hi) {
    ull d;
    asm("mov.b64 %0, {%1, %2};" : "=l"(d) : "r"(__float_as_uint(lo)), "r"(__float_as_uint(hi)));
    return d;
}
__device__ __forceinline__ ull fma2(ull a, ull b, ull c) {
    ull d;
    asm("fma.rn.f32x2 %0, %1, %2, %3;" : "=l"(d) : "l"(a), "l"(b), "l"(c));
    return d;
}
__device__ __forceinline__ void unpack2(ull v, float& lo, float& hi) {
    unsigned int l, h;
    asm("mov.b64 {%0, %1}, %2;" : "=r"(l), "=r"(h) : "l"(v));
    lo = __uint_as_float(l); hi = __uint_as_float(h);
}

// Charge-grouped split-K GEMM with INLINE stable classification (no prep
// kernel, no atomics -> fully deterministic):
// each block recomputes its own 64-row window of the charge-s segment via a
// block-wide prefix scan over the 2048-entry charges array (L1/L2-hot).
__global__ void __launch_bounds__(256)
k_gemm(const float* __restrict__ rep,
       const float* __restrict__ reductors,
       const int* __restrict__ charges) {
    int s = blockIdx.z;
    int row0 = blockIdx.y * BM;

    int ntile  = blockIdx.x & 3;
    int kslice = blockIdx.x >> 2;
    int k0 = kslice * KCHUNK;

    // float4 accesses into As/Bs require 16B alignment (R8 bug: warpPfx's
    // 36 bytes pushed As to offset 292 -> misaligned-address trap).
    __shared__ __align__(16) float As[BK][BM];
    __shared__ __align__(16) float Bs[BK][BN];
    __shared__ int   rowIdx[BM];
    __shared__ int   warpPfx[9];          // exclusive warp offsets + total

    int t    = threadIdx.x;
    int lane = t & 31;
    int w    = t >> 5;

    // ---- stable classification scan: rows t*8 .. t*8+7 ----
    if (t < BM) rowIdx[t] = -1;
    int base = t * 8;
    uint mymask = 0;
    #pragma unroll
    for (int j = 0; j < 8; j++)
        mymask |= (uint)(charges[base + j] == s) << j;
    int mycnt = __popc(mymask);
    // warp-inclusive scan of per-thread counts
    int incl = mycnt;
    #pragma unroll
    for (int off = 1; off < 32; off <<= 1) {
        int n = __shfl_up_sync(0xffffffffu, incl, off);
        if (lane >= off) incl += n;
    }
    if (lane == 31) warpPfx[w + 1] = incl;   // warp totals at [1..8]
    __syncthreads();
    if (t == 0) {
        warpPfx[0] = 0;
        int run = 0;
        #pragma unroll
        for (int i = 1; i <= 8; i++) { run += warpPfx[i]; warpPfx[i] = run; }
    }
    __syncthreads();
    int cnt = warpPfx[8];
    if (row0 >= cnt) return;
    int excl = warpPfx[w] + incl - mycnt;    // stable global rank of my first match
    #pragma unroll
    for (int j = 0; j < 8; j++) {
        if (mymask & (1u << j)) {
            int rk = excl++;
            int loc = rk - row0;
            if (loc >= 0 && loc < BM) rowIdx[loc] = base + j;
        }
    }
    __syncthreads();

    // ---- GEMM ----
    int tx = t & 15;
    int ty = t >> 4;

    ull acc2[4][2] = {};
    const float* redS = reductors + s * RDIM * PDIM + ntile * BN;

    for (int kb = k0; kb < k0 + KCHUNK; kb += BK) {
        #pragma unroll
        for (int i = 0; i < 2; i++) {
            int slot = t * 2 + i;
            int r  = slot >> 3;
            int kq = slot & 7;
            int grow = rowIdx[r];
            float4 v = make_float4(0.f, 0.f, 0.f, 0.f);
            if (grow >= 0)
                v = *(const float4*)(rep + grow * RDIM + kb + kq * 4);
            As[kq * 4 + 0][r] = v.x;
            As[kq * 4 + 1][r] = v.y;
            As[kq * 4 + 2][r] = v.z;
            As[kq * 4 + 3][r] = v.w;
        }
        #pragma unroll
        for (int i = 0; i < 2; i++) {
            int slot = t * 2 + i;
            int k  = slot >> 4;
            int cq = slot & 15;
            float4 v = *(const float4*)(redS + (kb + k) * PDIM + cq * 4);
            *(float4*)&Bs[k][cq * 4] = v;
        }
        __syncthreads();

        #pragma unroll
        for (int k = 0; k < BK; k++) {
            float4 a4 = *(const float4*)&As[k][ty * 4];
            float4 b4 = *(const float4*)&Bs[k][tx * 4];
            ull a01 = pack2(a4.x, a4.y);
            ull a23 = pack2(a4.z, a4.w);
            float bv[4] = {b4.x, b4.y, b4.z, b4.w};
            #pragma unroll
            for (int jj = 0; jj < 4; jj++) {
                ull bd = pack2(bv[jj], bv[jj]);
                acc2[jj][0] = fma2(a01, bd, acc2[jj][0]);
                acc2[jj][1] = fma2(a23, bd, acc2[jj][1]);
            }
        }
        __syncthreads();
    }

    float acc[4][4];
    #pragma unroll
    for (int jj = 0; jj < 4; jj++) {
        unpack2(acc2[jj][0], acc[0][jj], acc[1][jj]);
        unpack2(acc2[jj][1], acc[2][jj], acc[3][jj]);
    }

    float* outSlice = g_proj4 + kslice * (NROWS * PDIM);
    #pragma unroll
    for (int ii = 0; ii < 4; ii++) {
        int r = rowIdx[ty * 4 + ii];
        if (r >= 0) {
            float4 v = make_float4(acc[ii][0], acc[ii][1], acc[ii][2], acc[ii][3]);
            *(float4*)(outSlice + r * PDIM + ntile * BN + tx * 4) = v;
        }
    }
}

// One warp per (pair, stack-group): 8192 tasks. FWHT-256 with half-exchange
// lane stages: element (lane q, reg r) ends at logical index
// 128*(r>>2) + (q>>1)*8 + (q&1)*4 + (r&3); bias/alpha load at the matching
// permuted bases (two contiguous float4 runs). Alpha-dot is permutation
// invariant. (R5-proven shape: no threadfence, no fused reduce.)
__global__ void __launch_bounds__(256)
k_feat(const int* __restrict__ charges,
       const float* __restrict__ Dmat,
       const float* __restrict__ bias,
       const float* __restrict__ alpha) {
    int warpId = threadIdx.x >> 5;
    int lane   = threadIdx.x & 31;
    int task   = blockIdx.x * 8 + warpId;   // 0..8191
    int pair   = task >> 2;
    int grp    = task & 3;
    int st0    = grp * 8;

    int s = charges[pair];

    uint projb[8];
    {
        const float* pp = g_proj4 + pair * PDIM + lane * 8;
        float4 p0 = *(const float4*)pp;
        float4 p1 = *(const float4*)(pp + 4);
        float acc[8] = {p0.x, p0.y, p0.z, p0.w, p1.x, p1.y, p1.z, p1.w};
        #pragma unroll
        for (int c = 1; c < KSPLIT; c++) {
            const float* pc = g_proj4 + c * (NROWS * PDIM) + pair * PDIM + lane * 8;
            float4 q0 = *(const float4*)pc;
            float4 q1 = *(const float4*)(pc + 4);
            acc[0] += q0.x; acc[1] += q0.y; acc[2] += q0.z; acc[3] += q0.w;
            acc[4] += q1.x; acc[5] += q1.y; acc[6] += q1.z; acc[7] += q1.w;
        }
        // fold FWHT normalization 1/16 (COEFF_NORM == 1 exactly)
        #pragma unroll
        for (int j = 0; j < 8; j++) projb[j] = __float_as_uint(acc[j] * 0.0625f);
    }

    const float* Ds = Dmat + s * NSTACKS * PDIM;
    const float* bs = bias + s * NFEAT;
    int pbase = ((lane >> 1) << 3) + ((lane & 1) << 2);

    float sum = 0.f;
    for (int st = st0; st < st0 + 8; st++) {
        const uint4* dp = (const uint4*)(Ds + st * PDIM + lane * 8);
        uint4 d0 = dp[0];
        uint4 d1 = dp[1];
        uint db[8] = {d0.x, d0.y, d0.z, d0.w, d1.x, d1.y, d1.z, d1.w};
        float v[8];
        #pragma unroll
        for (int j = 0; j < 8; j++)
            v[j] = __uint_as_float(projb[j] ^ (db[j] & 0x80000000u));

        float tv;
        tv = v[0]; v[0] = tv + v[1]; v[1] = tv - v[1];
        tv = v[2]; v[2] = tv + v[3]; v[3] = tv - v[3];
        tv = v[4]; v[4] = tv + v[5]; v[5] = tv - v[5];
        tv = v[6]; v[6] = tv + v[7]; v[7] = tv - v[7];

        tv = v[0]; v[0] = tv + v[2]; v[2] = tv - v[2];
        tv = v[1]; v[1] = tv + v[3]; v[3] = tv - v[3];
        tv = v[4]; v[4] = tv + v[6]; v[6] = tv - v[6];
        tv = v[5]; v[5] = tv + v[7]; v[7] = tv - v[7];

        tv = v[0]; v[0] = tv + v[4]; v[4] = tv - v[4];
        tv = v[1]; v[1] = tv + v[5]; v[5] = tv - v[5];
        tv = v[2]; v[2] = tv + v[6]; v[6] = tv - v[6];
        tv = v[3]; v[3] = tv + v[7]; v[7] = tv - v[7];

        #pragma unroll
        for (int msk = 1; msk <= 16; msk <<= 1) {
            bool hi = (lane & msk) != 0;
            float sgn = hi ? -1.f : 1.f;
            float nv[8];
            #pragma unroll
            for (int r = 0; r < 4; r++) {
                float send = hi ? v[r]     : v[r + 4];
                float keep = hi ? v[r + 4] : v[r];
                float recv = __shfl_xor_sync(0xffffffffu, send, msk);
                nv[r]     = keep + recv;
                nv[r + 4] = (keep - recv) * sgn;
            }
            #pragma unroll
            for (int r = 0; r < 8; r++) v[r] = nv[r];
        }

        const float* bp = bs + st * PDIM + pbase;
        const float* ap = alpha + st * PDIM + pbase;
        float4 b0 = *(const float4*)bp;
        float4 b1 = *(const float4*)(bp + 128);
        float4 a0 = *(const float4*)ap;
        float4 a1 = *(const float4*)(ap + 128);
        float bb[8] = {b0.x, b0.y, b0.z, b0.w, b1.x, b1.y, b1.z, b1.w};
        float aa[8] = {a0.x, a0.y, a0.z, a0.w, a1.x, a1.y, a1.z, a1.w};
        #pragma unroll
        for (int j = 0; j < 8; j++)
            sum += __cosf(v[j] + bb[j]) * aa[j];
    }

    #pragma unroll
    for (int off = 16; off; off >>= 1)
        sum += __shfl_down_sync(0xffffffffu, sum, off);
    if (lane == 0) g_partial[task] = sum;   // task = m*256 + a*4 + grp
}

// out[m] = FEAT_NORM * sum over 256 contiguous partials
__global__ void k_reduce(float* __restrict__ out) {
    int m = blockIdx.x;
    int t = threadIdx.x;   // 256 threads
    float v = g_partial[m * 256 + t];
    #pragma unroll
    for (int off = 16; off; off >>= 1)
        v += __shfl_down_sync(0xffffffffu, v, off);
    __shared__ float sm8[8];
    if ((t & 31) == 0) sm8[t >> 5] = v;
    __syncthreads();
    if (t < 8) {
        float w = sm8[t];
        #pragma unroll
        for (int off = 4; off; off >>= 1)
            w += __shfl_down_sync(0xffu, w, off);
        if (t == 0) out[m] = 0.015625f * w;   // FEAT_NORM = 1/64
    }
}

extern "C" void kernel_launch(void* const* d_in, const int* in_sizes, int n_in,
                              void* d_out, int out_size) {
    const float* rep       = (const float*)d_in[0];
    const int*   charges   = (const int*)d_in[1];
    const float* reductors = (const float*)d_in[2];
    const float* Dmat      = (const float*)d_in[3];
    const float* bias      = (const float*)d_in[4];
    const float* alpha     = (const float*)d_in[5];
    float* out = (float*)d_out;

    dim3 gg(4 * KSPLIT, NROWS / BM, NS);   // (16, 32, 4); empty row-blocks exit early
    k_gemm<<<gg, 256>>>(rep, reductors, charges);
    k_feat<<<1024, 256>>>(charges, Dmat, bias, alpha);   // 8192 warps
    k_reduce<<<MROWS, 256>>>(out);
}